// round 1
// baseline (speedup 1.0000x reference)
#include <cuda_runtime.h>
#include <math.h>

#define D_MODEL 2048
#define N_HEADS 16
#define DH 128
#define BATCH 2
#define SEQ 2048
#define BS (BATCH * SEQ)  /* 4096 rows */

// ---------------------------------------------------------------------------
// Scratch (device globals; no allocation allowed)
// ---------------------------------------------------------------------------
__device__ float g_t0[(size_t)BS * D_MODEL];        // 32 MB  (pre-LN temp)
__device__ float g_cq[(size_t)BS * D_MODEL];        // 32 MB
__device__ float g_Q [(size_t)BS * D_MODEL];        // 32 MB
__device__ float g_KV[(size_t)BS * 2 * D_MODEL];    // 64 MB  (K | V)
__device__ float g_O [(size_t)BS * D_MODEL];        // 32 MB

// ---------------------------------------------------------------------------
// Generic tiled fp32 GEMM: C[M,N] = A[M,K] @ B  (B row-major [K,N], or if
// TRANSB, B row-major [N,K] and we compute A @ B^T).
// 128x128 block, BK=16, 256 threads, 8x8 per thread.
// ---------------------------------------------------------------------------
#define TILE_M 128
#define TILE_N 128
#define TILE_K 16
#define SPAD 132   // padded row length to dodge store bank conflicts

template <bool TRANSB>
__global__ __launch_bounds__(256)
void gemm_kernel(const float* __restrict__ A, const float* __restrict__ B,
                 float* __restrict__ C, int M, int N, int K)
{
    __shared__ float As[TILE_K][SPAD];
    __shared__ float Bs[TILE_K][SPAD];

    const int tid = threadIdx.x;
    const int tx = tid & 15;         // 0..15 (n direction)
    const int ty = tid >> 4;         // 0..15 (m direction)
    const int m0 = blockIdx.y * TILE_M;
    const int n0 = blockIdx.x * TILE_N;

    float acc[8][8];
#pragma unroll
    for (int i = 0; i < 8; i++)
#pragma unroll
        for (int j = 0; j < 8; j++) acc[i][j] = 0.f;

    for (int k0 = 0; k0 < K; k0 += TILE_K) {
        // --- load A tile (128 x 16), store transposed As[k][m] ---
#pragma unroll
        for (int it = 0; it < 2; it++) {
            int f = it * 256 + tid;          // 0..511
            int row = f >> 2;                // 0..127
            int k4 = f & 3;                  // 0..3 (float4 along k)
            float4 v = *(const float4*)&A[(size_t)(m0 + row) * K + k0 + k4 * 4];
            As[k4 * 4 + 0][row] = v.x;
            As[k4 * 4 + 1][row] = v.y;
            As[k4 * 4 + 2][row] = v.z;
            As[k4 * 4 + 3][row] = v.w;
        }
        // --- load B tile -> Bs[k][n] ---
        if (!TRANSB) {
#pragma unroll
            for (int it = 0; it < 2; it++) {
                int f = it * 256 + tid;      // 0..511
                int kr = f >> 5;             // 0..15
                int c4 = f & 31;             // 0..31
                float4 v = *(const float4*)&B[(size_t)(k0 + kr) * N + n0 + c4 * 4];
                *(float4*)&Bs[kr][c4 * 4] = v;
            }
        } else {
#pragma unroll
            for (int it = 0; it < 2; it++) {
                int f = it * 256 + tid;      // 0..511
                int nr = f >> 2;             // 0..127
                int k4 = f & 3;              // 0..3
                float4 v = *(const float4*)&B[(size_t)(n0 + nr) * K + k0 + k4 * 4];
                Bs[k4 * 4 + 0][nr] = v.x;
                Bs[k4 * 4 + 1][nr] = v.y;
                Bs[k4 * 4 + 2][nr] = v.z;
                Bs[k4 * 4 + 3][nr] = v.w;
            }
        }
        __syncthreads();

#pragma unroll
        for (int kk = 0; kk < TILE_K; kk++) {
            float ra[8], rb[8];
            *(float4*)&ra[0] = *(const float4*)&As[kk][ty * 8];
            *(float4*)&ra[4] = *(const float4*)&As[kk][ty * 8 + 4];
            *(float4*)&rb[0] = *(const float4*)&Bs[kk][tx * 8];
            *(float4*)&rb[4] = *(const float4*)&Bs[kk][tx * 8 + 4];
#pragma unroll
            for (int i = 0; i < 8; i++)
#pragma unroll
                for (int j = 0; j < 8; j++)
                    acc[i][j] = fmaf(ra[i], rb[j], acc[i][j]);
        }
        __syncthreads();
    }

#pragma unroll
    for (int i = 0; i < 8; i++) {
        float* crow = &C[(size_t)(m0 + ty * 8 + i) * N + n0 + tx * 8];
        *(float4*)&crow[0] = make_float4(acc[i][0], acc[i][1], acc[i][2], acc[i][3]);
        *(float4*)&crow[4] = make_float4(acc[i][4], acc[i][5], acc[i][6], acc[i][7]);
    }
}

// ---------------------------------------------------------------------------
// LayerNorm over rows of length 2048. One block (256 threads) per row.
// ---------------------------------------------------------------------------
__device__ __forceinline__ float block_reduce_sum(float v, float* red)
{
    __syncthreads();   // protect red reuse across calls
    int lane = threadIdx.x & 31;
    int w = threadIdx.x >> 5;     // 0..7
#pragma unroll
    for (int o = 16; o; o >>= 1) v += __shfl_xor_sync(0xffffffffu, v, o);
    if (lane == 0) red[w] = v;
    __syncthreads();
    float t = 0.f;
#pragma unroll
    for (int i = 0; i < 8; i++) t += red[i];
    return t;
}

__global__ __launch_bounds__(256)
void layernorm_kernel(const float* __restrict__ in, const float* __restrict__ gamma,
                      const float* __restrict__ beta, float* __restrict__ out)
{
    __shared__ float red[8];
    const int row = blockIdx.x;
    const float* x = in + (size_t)row * D_MODEL;

    float v[8];
    float s = 0.f;
#pragma unroll
    for (int i = 0; i < 8; i++) {
        v[i] = x[threadIdx.x + i * 256];
        s += v[i];
    }
    s = block_reduce_sum(s, red);
    const float mu = s * (1.f / (float)D_MODEL);

    float sq = 0.f;
#pragma unroll
    for (int i = 0; i < 8; i++) {
        float d = v[i] - mu;
        sq = fmaf(d, d, sq);
    }
    sq = block_reduce_sum(sq, red);
    const float inv = rsqrtf(sq * (1.f / (float)D_MODEL) + 1e-5f);

    float* y = out + (size_t)row * D_MODEL;
#pragma unroll
    for (int i = 0; i < 8; i++) {
        int c = threadIdx.x + i * 256;
        y[c] = (v[i] - mu) * inv * gamma[c] + beta[c];
    }
}

// ---------------------------------------------------------------------------
// RoPE, applied in place to Q ([B,S,D] head-interleaved) and K (first half of
// KV [B,S,2D]). One thread per (b, s, h, i) rotation pair, i in [0,64).
// ---------------------------------------------------------------------------
__global__ __launch_bounds__(256)
void rope_kernel(float* __restrict__ Q, float* __restrict__ KV)
{
    int idx = blockIdx.x * blockDim.x + threadIdx.x;   // 2^22 total
    int i = idx & 63;
    int h = (idx >> 6) & (N_HEADS - 1);
    int s = (idx >> 10) & (SEQ - 1);
    int b = idx >> 21;

    float freq = powf(10000.0f, -(float)i * (1.0f / 64.0f));
    float sn, cs;
    sincosf((float)s * freq, &sn, &cs);

    size_t qb = ((size_t)(b * SEQ + s)) * D_MODEL + h * DH;
    float q1 = Q[qb + i], q2 = Q[qb + i + 64];
    Q[qb + i]      = q1 * cs - q2 * sn;
    Q[qb + i + 64] = q2 * cs + q1 * sn;

    size_t kb = ((size_t)(b * SEQ + s)) * (2 * D_MODEL) + h * DH;
    float k1 = KV[kb + i], k2 = KV[kb + i + 64];
    KV[kb + i]      = k1 * cs - k2 * sn;
    KV[kb + i + 64] = k2 * cs + k1 * sn;
}

// ---------------------------------------------------------------------------
// Causal flash attention (fp32, online softmax).
// grid (S/64, H, B), 128 threads. Thread pair (2r, 2r+1) owns query row r of
// the 64-row q-tile; each thread handles 64 of the 128 head dims. K/V tiles of
// 32 rows staged in smem; K reads broadcast across the warp.
// ---------------------------------------------------------------------------
#define QT 64
#define KT 32
#define NEG_BIG (-1e30f)

__global__ __launch_bounds__(128, 2)
void flash_attn_kernel(const float* __restrict__ Q, const float* __restrict__ KV,
                       float* __restrict__ O)
{
    __shared__ float Ks[KT][DH];
    __shared__ float Vs[KT][DH];

    const int qt = blockIdx.x, h = blockIdx.y, b = blockIdx.z;
    const int tid = threadIdx.x;
    const int row = tid >> 1;
    const int half = tid & 1;
    const int s_q = qt * QT + row;
    const float scale = 0.088388347648318447f;  // 1/sqrt(128)

    // load + pre-scale q (64 floats per thread)
    float q[64];
    {
        const float* qp = Q + ((size_t)(b * SEQ + s_q)) * D_MODEL + h * DH + half * 64;
#pragma unroll
        for (int i = 0; i < 16; i++) {
            float4 t = *(const float4*)&qp[i * 4];
            q[i * 4 + 0] = t.x * scale;
            q[i * 4 + 1] = t.y * scale;
            q[i * 4 + 2] = t.z * scale;
            q[i * 4 + 3] = t.w * scale;
        }
    }

    float o[64];
#pragma unroll
    for (int i = 0; i < 64; i++) o[i] = 0.f;
    float m = NEG_BIG, l = 0.f;

    const int kend = qt * QT + QT;   // exclusive; causal skip of later tiles
    for (int j0 = 0; j0 < kend; j0 += KT) {
        // stage K and V tiles (coalesced, each thread 8 float4 per tensor)
#pragma unroll
        for (int i = 0; i < 8; i++) {
            int f = i * 128 + tid;           // 0..1023
            int r = f >> 5, c = f & 31;
            size_t g = ((size_t)(b * SEQ + j0 + r)) * (2 * D_MODEL) + h * DH + c * 4;
            *(float4*)&Ks[r][c * 4] = *(const float4*)&KV[g];
            *(float4*)&Vs[r][c * 4] = *(const float4*)&KV[g + D_MODEL];
        }
        __syncthreads();

        // scores for this tile
        float sc[KT];
#pragma unroll
        for (int j = 0; j < KT; j++) {
            const float* kr = &Ks[j][half * 64];
            float p0 = 0.f, p1 = 0.f, p2 = 0.f, p3 = 0.f;
#pragma unroll
            for (int d = 0; d < 64; d += 4) {
                float4 kv4 = *(const float4*)&kr[d];
                p0 = fmaf(q[d + 0], kv4.x, p0);
                p1 = fmaf(q[d + 1], kv4.y, p1);
                p2 = fmaf(q[d + 2], kv4.z, p2);
                p3 = fmaf(q[d + 3], kv4.w, p3);
            }
            float partial = (p0 + p1) + (p2 + p3);
            float full = partial + __shfl_xor_sync(0xffffffffu, partial, 1);
            sc[j] = (j0 + j <= s_q) ? full : NEG_BIG;
        }

        // online softmax update
        float mt = NEG_BIG;
#pragma unroll
        for (int j = 0; j < KT; j++) mt = fmaxf(mt, sc[j]);
        float m_new = fmaxf(m, mt);
        float corr = __expf(m - m_new);
        m = m_new;
        l *= corr;
#pragma unroll
        for (int i = 0; i < 64; i++) o[i] *= corr;

#pragma unroll
        for (int j = 0; j < KT; j++) {
            float p = __expf(sc[j] - m_new);
            l += p;
            const float* vr = &Vs[j][half * 64];
#pragma unroll
            for (int d = 0; d < 64; d += 4) {
                float4 vv = *(const float4*)&vr[d];
                o[d + 0] = fmaf(p, vv.x, o[d + 0]);
                o[d + 1] = fmaf(p, vv.y, o[d + 1]);
                o[d + 2] = fmaf(p, vv.z, o[d + 2]);
                o[d + 3] = fmaf(p, vv.w, o[d + 3]);
            }
        }
        __syncthreads();
    }

    const float inv_l = 1.f / l;
    float* op = O + ((size_t)(b * SEQ + s_q)) * D_MODEL + h * DH + half * 64;
#pragma unroll
    for (int i = 0; i < 16; i++) {
        *(float4*)&op[i * 4] = make_float4(o[i * 4 + 0] * inv_l, o[i * 4 + 1] * inv_l,
                                           o[i * 4 + 2] * inv_l, o[i * 4 + 3] * inv_l);
    }
}

// ---------------------------------------------------------------------------
// Launch
// Inputs (metadata order): x, W_dq, W_uq, q_gamma, q_beta, W_dkv, W_ukv,
//                          kv_gamma, kv_beta, W_o
// Outputs: d_out[0 : BS*D]       = out
//          d_out[BS*D : 2*BS*D]  = ckv
// ---------------------------------------------------------------------------
extern "C" void kernel_launch(void* const* d_in, const int* in_sizes, int n_in,
                              void* d_out, int out_size)
{
    const float* x        = (const float*)d_in[0];
    const float* W_dq     = (const float*)d_in[1];
    const float* W_uq     = (const float*)d_in[2];
    const float* q_gamma  = (const float*)d_in[3];
    const float* q_beta   = (const float*)d_in[4];
    const float* W_dkv    = (const float*)d_in[5];
    const float* W_ukv    = (const float*)d_in[6];
    const float* kv_gamma = (const float*)d_in[7];
    const float* kv_beta  = (const float*)d_in[8];
    const float* W_o      = (const float*)d_in[9];

    float* out = (float*)d_out;
    float* ckv = out + (size_t)BS * D_MODEL;

    float *t0, *cq, *Qb, *KVb, *Ob;
    cudaGetSymbolAddress((void**)&t0, g_t0);
    cudaGetSymbolAddress((void**)&cq, g_cq);
    cudaGetSymbolAddress((void**)&Qb, g_Q);
    cudaGetSymbolAddress((void**)&KVb, g_KV);
    cudaGetSymbolAddress((void**)&Ob, g_O);

    dim3 gDD(D_MODEL / TILE_N, BS / TILE_M);       // (16, 32)
    dim3 gD2D(2 * D_MODEL / TILE_N, BS / TILE_M);  // (32, 32)

    // Q path
    gemm_kernel<false><<<gDD, 256>>>(x, W_dq, t0, BS, D_MODEL, D_MODEL);
    layernorm_kernel<<<BS, 256>>>(t0, q_gamma, q_beta, cq);
    gemm_kernel<false><<<gDD, 256>>>(cq, W_uq, Qb, BS, D_MODEL, D_MODEL);
    // KV path (ckv lands directly in the output buffer)
    gemm_kernel<false><<<gDD, 256>>>(x, W_dkv, t0, BS, D_MODEL, D_MODEL);
    layernorm_kernel<<<BS, 256>>>(t0, kv_gamma, kv_beta, ckv);
    gemm_kernel<false><<<gD2D, 256>>>(ckv, W_ukv, KVb, BS, 2 * D_MODEL, D_MODEL);
    // RoPE on Q and K
    rope_kernel<<<(BATCH * SEQ * N_HEADS * 64) / 256, 256>>>(Qb, KVb);
    // causal attention
    flash_attn_kernel<<<dim3(SEQ / QT, N_HEADS, BATCH), 128>>>(Qb, KVb, Ob);
    // output projection: out = O @ W_o^T
    gemm_kernel<true><<<gDD, 256>>>(Ob, W_o, out, BS, D_MODEL, D_MODEL);
}

// round 4
// speedup vs baseline: 1.7555x; 1.7555x over previous
#include <cuda_runtime.h>
#include <cuda_bf16.h>
#include <math.h>
#include <stdint.h>

#define D_MODEL 2048
#define N_HEADS 16
#define DH 128
#define BATCH 2
#define SEQ 2048
#define BS (BATCH * SEQ)  /* 4096 rows */

typedef __nv_bfloat16 bf16;

// ---------------------------------------------------------------------------
// Scratch (device globals; no allocation allowed)
// ---------------------------------------------------------------------------
__device__ float g_t0[(size_t)BS * D_MODEL];
__device__ float g_cq[(size_t)BS * D_MODEL];
__device__ float g_Q [(size_t)BS * D_MODEL];
__device__ float g_KV[(size_t)BS * 2 * D_MODEL];
__device__ float g_O [(size_t)BS * D_MODEL];
__device__ bf16  g_Ahi[(size_t)4096 * 2048];
__device__ bf16  g_Alo[(size_t)4096 * 2048];
__device__ bf16  g_Bhi[(size_t)4096 * 2048];
__device__ bf16  g_Blo[(size_t)4096 * 2048];

// ---------------------------------------------------------------------------
// Baseline-PTX helpers (all sm_80+, legal under compute_103 virtual arch)
// ---------------------------------------------------------------------------
__device__ __forceinline__ uint32_t smem_to_u32(const void* p) {
    uint32_t a;
    asm("{ .reg .u64 t; cvta.to.shared.u64 t, %1; cvt.u32.u64 %0, t; }" : "=r"(a) : "l"(p));
    return a;
}

#define CP_ASYNC16(s, g) \
    asm volatile("cp.async.cg.shared.global [%0], [%1], 16;" :: "r"(s), "l"(g))
#define CP_COMMIT() asm volatile("cp.async.commit_group;")
#define CP_WAIT1()  asm volatile("cp.async.wait_group 1;")

__device__ __forceinline__ void ldsm4(uint32_t* r, uint32_t a) {
    asm volatile("ldmatrix.sync.aligned.m8n8.x4.shared.b16 {%0,%1,%2,%3}, [%4];"
        : "=r"(r[0]), "=r"(r[1]), "=r"(r[2]), "=r"(r[3]) : "r"(a));
}

__device__ __forceinline__ void mma16816(float* d, const uint32_t* a, uint32_t b0, uint32_t b1) {
    asm volatile(
        "mma.sync.aligned.m16n8k16.row.col.f32.bf16.bf16.f32 "
        "{%0,%1,%2,%3}, {%4,%5,%6,%7}, {%8,%9}, {%0,%1,%2,%3};"
        : "+f"(d[0]), "+f"(d[1]), "+f"(d[2]), "+f"(d[3])
        : "r"(a[0]), "r"(a[1]), "r"(a[2]), "r"(a[3]), "r"(b0), "r"(b1));
}

// SW128 swizzle (byte-offset XOR, 16B granular)
#define SW128(off) ((off) ^ (((off) >> 3) & 0x70))

// ---------------------------------------------------------------------------
// Hi/Lo bf16 split conversion (row-major)
// ---------------------------------------------------------------------------
__global__ __launch_bounds__(256)
void conv_hl(const float* __restrict__ s, bf16* __restrict__ hi, bf16* __restrict__ lo, int n4)
{
    int i = blockIdx.x * blockDim.x + threadIdx.x;
    if (i >= n4) return;
    float4 v = ((const float4*)s)[i];
    bf16 h0 = __float2bfloat16(v.x), h1 = __float2bfloat16(v.y);
    bf16 h2 = __float2bfloat16(v.z), h3 = __float2bfloat16(v.w);
    __nv_bfloat162* hp = (__nv_bfloat162*)(hi + (size_t)i * 4);
    __nv_bfloat162* lp = (__nv_bfloat162*)(lo + (size_t)i * 4);
    hp[0] = __nv_bfloat162(h0, h1);
    hp[1] = __nv_bfloat162(h2, h3);
    lp[0] = __nv_bfloat162(__float2bfloat16(v.x - __bfloat162float(h0)),
                           __float2bfloat16(v.y - __bfloat162float(h1)));
    lp[1] = __nv_bfloat162(__float2bfloat16(v.z - __bfloat162float(h2)),
                           __float2bfloat16(v.w - __bfloat162float(h3)));
}

// Hi/Lo split + transpose: src fp32 [K,N] -> dst bf16 [N,K]
__global__ __launch_bounds__(256)
void convt_hl(const float* __restrict__ s, bf16* __restrict__ hi, bf16* __restrict__ lo,
              int K, int N)
{
    __shared__ float t[32][33];
    int tx = threadIdx.x & 31, ty = threadIdx.x >> 5;  // 32 x 8
    int n0 = blockIdx.x * 32, k0 = blockIdx.y * 32;
#pragma unroll
    for (int i = 0; i < 4; i++)
        t[ty + i * 8][tx] = s[(size_t)(k0 + ty + i * 8) * N + n0 + tx];
    __syncthreads();
#pragma unroll
    for (int i = 0; i < 4; i++) {
        float v = t[tx][ty + i * 8];
        bf16 h = __float2bfloat16(v);
        size_t o = (size_t)(n0 + ty + i * 8) * K + k0 + tx;
        hi[o] = h;
        lo[o] = __float2bfloat16(v - __bfloat162float(h));
    }
}

// ---------------------------------------------------------------------------
// mma.sync bf16x3 GEMM: C[M,N] = A @ B^T, A [M,K] and B [N,K] both K-major
// hi/lo pairs. 128x128 CTA tile, 8 warps (2x4), 64x32 warp tile, BK=64,
// cp.async double buffering, fp32 accum.
// ---------------------------------------------------------------------------
#define BK 64
#define TILE_BYTES 16384               // 128 rows x 128 B
#define BUF_BYTES  (4 * TILE_BYTES)    // Ahi|Alo|Bhi|Blo
#define MG_SMEM    (2 * BUF_BYTES)     // 131072

__global__ __launch_bounds__(256, 1)
void mma_gemm(const bf16* __restrict__ Ahi, const bf16* __restrict__ Alo,
              const bf16* __restrict__ Bhi, const bf16* __restrict__ Blo,
              float* __restrict__ C, int M, int N, int K)
{
    extern __shared__ char sm[];
    const uint32_t sb = smem_to_u32(sm);
    const int tid = threadIdx.x, wid = tid >> 5, lane = tid & 31;
    const int m0 = blockIdx.y * 128, n0 = blockIdx.x * 128;
    const int warp_m = (wid & 1) * 64, warp_n = (wid >> 1) * 32;
    const int nch = K >> 6;   // 32

    // ldmatrix per-lane address components
    const int q = lane >> 3, r = lane & 7;
    const int arow = (q & 1) * 8 + r, akcol = (q >> 1) * 8;   // A quads
    const int brow = (q >> 1) * 8 + r, bkcol = (q & 1) * 8;   // B quads

    auto issue_chunk = [&](int k0, int buf) {
#pragma unroll
        for (int t = 0; t < 4; t++) {
            const bf16* base = (t == 0) ? Ahi : (t == 1) ? Alo : (t == 2) ? Bhi : Blo;
            const int rb = (t < 2) ? m0 : n0;
#pragma unroll
            for (int it = 0; it < 4; it++) {
                int f = it * 256 + tid;          // 0..1023
                int rr = f >> 3, c = f & 7;      // row, 16B-chunk
                const bf16* g = base + (size_t)(rb + rr) * K + k0 + c * 8;
                uint32_t s = sb + (uint32_t)(buf * BUF_BYTES + t * TILE_BYTES)
                           + SW128(rr * 128 + c * 16);
                CP_ASYNC16(s, g);
            }
        }
        CP_COMMIT();
    };

    float acc[4][4][4];
#pragma unroll
    for (int i = 0; i < 4; i++)
#pragma unroll
        for (int j = 0; j < 4; j++)
#pragma unroll
            for (int k = 0; k < 4; k++) acc[i][j][k] = 0.f;

    issue_chunk(0, 0);
    issue_chunk(BK, 1);

    for (int i = 0; i < nch; i++) {
        CP_WAIT1();
        __syncthreads();
        const uint32_t tb = sb + (uint32_t)((i & 1) * BUF_BYTES);

#pragma unroll
        for (int ks = 0; ks < 4; ks++) {
            uint32_t fa_hi[4][4], fa_lo[4][4], fb_hi[2][4], fb_lo[2][4];
#pragma unroll
            for (int mt = 0; mt < 4; mt++) {
                uint32_t off = SW128((warp_m + mt * 16 + arow) * 128 + (ks * 16 + akcol) * 2);
                ldsm4(fa_hi[mt], tb + off);
                ldsm4(fa_lo[mt], tb + TILE_BYTES + off);
            }
#pragma unroll
            for (int p = 0; p < 2; p++) {
                uint32_t off = SW128((warp_n + p * 16 + brow) * 128 + (ks * 16 + bkcol) * 2);
                ldsm4(fb_hi[p], tb + 2 * TILE_BYTES + off);
                ldsm4(fb_lo[p], tb + 3 * TILE_BYTES + off);
            }
#pragma unroll
            for (int mt = 0; mt < 4; mt++) {
#pragma unroll
                for (int nt = 0; nt < 4; nt++) {
                    uint32_t b0h = fb_hi[nt >> 1][(nt & 1) * 2];
                    uint32_t b1h = fb_hi[nt >> 1][(nt & 1) * 2 + 1];
                    uint32_t b0l = fb_lo[nt >> 1][(nt & 1) * 2];
                    uint32_t b1l = fb_lo[nt >> 1][(nt & 1) * 2 + 1];
                    mma16816(acc[mt][nt], fa_hi[mt], b0h, b1h);
                    mma16816(acc[mt][nt], fa_hi[mt], b0l, b1l);
                    mma16816(acc[mt][nt], fa_lo[mt], b0h, b1h);
                }
            }
        }
        __syncthreads();
        if (i + 2 < nch) issue_chunk((i + 2) * BK, i & 1);
    }

    // epilogue: accum fragment -> C (row = groupID(+8), cols = (lane%4)*2)
    const int grow = lane >> 2, gcol = (lane & 3) * 2;
#pragma unroll
    for (int mt = 0; mt < 4; mt++) {
#pragma unroll
        for (int nt = 0; nt < 4; nt++) {
            float* c0 = C + (size_t)(m0 + warp_m + mt * 16 + grow) * N
                          + n0 + warp_n + nt * 8 + gcol;
            *(float2*)c0 = make_float2(acc[mt][nt][0], acc[mt][nt][1]);
            *(float2*)(c0 + (size_t)8 * N) = make_float2(acc[mt][nt][2], acc[mt][nt][3]);
        }
    }
}

// ---------------------------------------------------------------------------
// LayerNorm (rows of 2048), one 256-thread block per row
// ---------------------------------------------------------------------------
__device__ __forceinline__ float block_reduce_sum(float v, float* red)
{
    __syncthreads();
    int lane = threadIdx.x & 31;
    int w = threadIdx.x >> 5;
#pragma unroll
    for (int o = 16; o; o >>= 1) v += __shfl_xor_sync(0xffffffffu, v, o);
    if (lane == 0) red[w] = v;
    __syncthreads();
    float t = 0.f;
#pragma unroll
    for (int i = 0; i < 8; i++) t += red[i];
    return t;
}

__global__ __launch_bounds__(256)
void layernorm_kernel(const float* __restrict__ in, const float* __restrict__ gamma,
                      const float* __restrict__ beta, float* __restrict__ out)
{
    __shared__ float red[8];
    const int row = blockIdx.x;
    const float* x = in + (size_t)row * D_MODEL;

    float v[8];
    float s = 0.f;
#pragma unroll
    for (int i = 0; i < 8; i++) { v[i] = x[threadIdx.x + i * 256]; s += v[i]; }
    s = block_reduce_sum(s, red);
    const float mu = s * (1.f / (float)D_MODEL);

    float sq = 0.f;
#pragma unroll
    for (int i = 0; i < 8; i++) { float d = v[i] - mu; sq = fmaf(d, d, sq); }
    sq = block_reduce_sum(sq, red);
    const float inv = rsqrtf(sq * (1.f / (float)D_MODEL) + 1e-5f);

    float* y = out + (size_t)row * D_MODEL;
#pragma unroll
    for (int i = 0; i < 8; i++) {
        int c = threadIdx.x + i * 256;
        y[c] = (v[i] - mu) * inv * gamma[c] + beta[c];
    }
}

// ---------------------------------------------------------------------------
// RoPE in place on Q and K (first half of KV)
// ---------------------------------------------------------------------------
__global__ __launch_bounds__(256)
void rope_kernel(float* __restrict__ Q, float* __restrict__ KV)
{
    int idx = blockIdx.x * blockDim.x + threadIdx.x;
    int i = idx & 63;
    int h = (idx >> 6) & (N_HEADS - 1);
    int s = (idx >> 10) & (SEQ - 1);
    int b = idx >> 21;

    float freq = powf(10000.0f, -(float)i * (1.0f / 64.0f));
    float sn, cs;
    sincosf((float)s * freq, &sn, &cs);

    size_t qb = ((size_t)(b * SEQ + s)) * D_MODEL + h * DH;
    float q1 = Q[qb + i], q2 = Q[qb + i + 64];
    Q[qb + i]      = q1 * cs - q2 * sn;
    Q[qb + i + 64] = q2 * cs + q1 * sn;

    size_t kb = ((size_t)(b * SEQ + s)) * (2 * D_MODEL) + h * DH;
    float k1 = KV[kb + i], k2 = KV[kb + i + 64];
    KV[kb + i]      = k1 * cs - k2 * sn;
    KV[kb + i + 64] = k2 * cs + k1 * sn;
}

// ---------------------------------------------------------------------------
// Causal flash attention (fp32, online softmax) — unchanged from R1 (passing)
// ---------------------------------------------------------------------------
#define QT 64
#define KT 32
#define NEG_BIG (-1e30f)

__global__ __launch_bounds__(128, 2)
void flash_attn_kernel(const float* __restrict__ Q, const float* __restrict__ KV,
                       float* __restrict__ O)
{
    __shared__ float Ks[KT][DH];
    __shared__ float Vs[KT][DH];

    const int qt = blockIdx.x, h = blockIdx.y, b = blockIdx.z;
    const int tid = threadIdx.x;
    const int row = tid >> 1;
    const int half = tid & 1;
    const int s_q = qt * QT + row;
    const float scale = 0.088388347648318447f;

    float q[64];
    {
        const float* qp = Q + ((size_t)(b * SEQ + s_q)) * D_MODEL + h * DH + half * 64;
#pragma unroll
        for (int i = 0; i < 16; i++) {
            float4 t = *(const float4*)&qp[i * 4];
            q[i * 4 + 0] = t.x * scale; q[i * 4 + 1] = t.y * scale;
            q[i * 4 + 2] = t.z * scale; q[i * 4 + 3] = t.w * scale;
        }
    }

    float o[64];
#pragma unroll
    for (int i = 0; i < 64; i++) o[i] = 0.f;
    float m = NEG_BIG, l = 0.f;

    const int kend = qt * QT + QT;
    for (int j0 = 0; j0 < kend; j0 += KT) {
#pragma unroll
        for (int i = 0; i < 8; i++) {
            int f = i * 128 + tid;
            int r = f >> 5, c = f & 31;
            size_t g = ((size_t)(b * SEQ + j0 + r)) * (2 * D_MODEL) + h * DH + c * 4;
            *(float4*)&Ks[r][c * 4] = *(const float4*)&KV[g];
            *(float4*)&Vs[r][c * 4] = *(const float4*)&KV[g + D_MODEL];
        }
        __syncthreads();

        float sc[KT];
#pragma unroll
        for (int j = 0; j < KT; j++) {
            const float* kr = &Ks[j][half * 64];
            float p0 = 0.f, p1 = 0.f, p2 = 0.f, p3 = 0.f;
#pragma unroll
            for (int d = 0; d < 64; d += 4) {
                float4 kv4 = *(const float4*)&kr[d];
                p0 = fmaf(q[d + 0], kv4.x, p0);
                p1 = fmaf(q[d + 1], kv4.y, p1);
                p2 = fmaf(q[d + 2], kv4.z, p2);
                p3 = fmaf(q[d + 3], kv4.w, p3);
            }
            float partial = (p0 + p1) + (p2 + p3);
            float full = partial + __shfl_xor_sync(0xffffffffu, partial, 1);
            sc[j] = (j0 + j <= s_q) ? full : NEG_BIG;
        }

        float mt = NEG_BIG;
#pragma unroll
        for (int j = 0; j < KT; j++) mt = fmaxf(mt, sc[j]);
        float m_new = fmaxf(m, mt);
        float corr = __expf(m - m_new);
        m = m_new;
        l *= corr;
#pragma unroll
        for (int i = 0; i < 64; i++) o[i] *= corr;

#pragma unroll
        for (int j = 0; j < KT; j++) {
            float p = __expf(sc[j] - m_new);
            l += p;
            const float* vr = &Vs[j][half * 64];
#pragma unroll
            for (int d = 0; d < 64; d += 4) {
                float4 vv = *(const float4*)&vr[d];
                o[d + 0] = fmaf(p, vv.x, o[d + 0]);
                o[d + 1] = fmaf(p, vv.y, o[d + 1]);
                o[d + 2] = fmaf(p, vv.z, o[d + 2]);
                o[d + 3] = fmaf(p, vv.w, o[d + 3]);
            }
        }
        __syncthreads();
    }

    const float inv_l = 1.f / l;
    float* op = O + ((size_t)(b * SEQ + s_q)) * D_MODEL + h * DH + half * 64;
#pragma unroll
    for (int i = 0; i < 16; i++) {
        *(float4*)&op[i * 4] = make_float4(o[i * 4 + 0] * inv_l, o[i * 4 + 1] * inv_l,
                                           o[i * 4 + 2] * inv_l, o[i * 4 + 3] * inv_l);
    }
}

// ---------------------------------------------------------------------------
// Launch
// ---------------------------------------------------------------------------
extern "C" void kernel_launch(void* const* d_in, const int* in_sizes, int n_in,
                              void* d_out, int out_size)
{
    const float* x        = (const float*)d_in[0];
    const float* W_dq     = (const float*)d_in[1];
    const float* W_uq     = (const float*)d_in[2];
    const float* q_gamma  = (const float*)d_in[3];
    const float* q_beta   = (const float*)d_in[4];
    const float* W_dkv    = (const float*)d_in[5];
    const float* W_ukv    = (const float*)d_in[6];
    const float* kv_gamma = (const float*)d_in[7];
    const float* kv_beta  = (const float*)d_in[8];
    const float* W_o      = (const float*)d_in[9];

    float* out = (float*)d_out;
    float* ckv = out + (size_t)BS * D_MODEL;

    float *t0, *cq, *Qb, *KVb, *Ob;
    bf16 *Ahi, *Alo, *Bhi, *Blo;
    cudaGetSymbolAddress((void**)&t0, g_t0);
    cudaGetSymbolAddress((void**)&cq, g_cq);
    cudaGetSymbolAddress((void**)&Qb, g_Q);
    cudaGetSymbolAddress((void**)&KVb, g_KV);
    cudaGetSymbolAddress((void**)&Ob, g_O);
    cudaGetSymbolAddress((void**)&Ahi, g_Ahi);
    cudaGetSymbolAddress((void**)&Alo, g_Alo);
    cudaGetSymbolAddress((void**)&Bhi, g_Bhi);
    cudaGetSymbolAddress((void**)&Blo, g_Blo);

    cudaFuncSetAttribute(mma_gemm, cudaFuncAttributeMaxDynamicSharedMemorySize, MG_SMEM);

    const int D = D_MODEL;
    const int nA = BS * D / 4 / 256;
    const int nW = D * D / 4 / 256;
    dim3 tpDD(D / 32, D / 32);
    dim3 tpD2D(2 * D / 32, D / 32);
    dim3 gDD(D / 128, BS / 128);       // (16, 32)
    dim3 gD2D(2 * D / 128, BS / 128);  // (32, 32)

    // --- x -> hi/lo (shared by both down-proj GEMMs) ---
    conv_hl<<<nA, 256>>>(x, Ahi, Alo, BS * D / 4);

    // Q down-proj + LN
    convt_hl<<<tpDD, 256>>>(W_dq, Bhi, Blo, D, D);
    mma_gemm<<<gDD, 256, MG_SMEM>>>(Ahi, Alo, Bhi, Blo, t0, BS, D, D);
    layernorm_kernel<<<BS, 256>>>(t0, q_gamma, q_beta, cq);

    // KV down-proj + LN (ckv straight into output buffer)
    convt_hl<<<tpDD, 256>>>(W_dkv, Bhi, Blo, D, D);
    mma_gemm<<<gDD, 256, MG_SMEM>>>(Ahi, Alo, Bhi, Blo, t0, BS, D, D);
    layernorm_kernel<<<BS, 256>>>(t0, kv_gamma, kv_beta, ckv);

    // Q up-proj
    conv_hl<<<nA, 256>>>(cq, Ahi, Alo, BS * D / 4);
    convt_hl<<<tpDD, 256>>>(W_uq, Bhi, Blo, D, D);
    mma_gemm<<<gDD, 256, MG_SMEM>>>(Ahi, Alo, Bhi, Blo, Qb, BS, D, D);

    // KV up-proj
    conv_hl<<<nA, 256>>>(ckv, Ahi, Alo, BS * D / 4);
    convt_hl<<<tpD2D, 256>>>(W_ukv, Bhi, Blo, D, 2 * D);
    mma_gemm<<<gD2D, 256, MG_SMEM>>>(Ahi, Alo, Bhi, Blo, KVb, BS, 2 * D, D);

    // RoPE + attention
    rope_kernel<<<(BATCH * SEQ * N_HEADS * 64) / 256, 256>>>(Qb, KVb);
    flash_attn_kernel<<<dim3(SEQ / QT, N_HEADS, BATCH), 128>>>(Qb, KVb, Ob);

    // Output projection: out = O @ W_o^T (W_o already [N,K] row-major)
    conv_hl<<<nA, 256>>>(Ob, Ahi, Alo, BS * D / 4);
    conv_hl<<<nW, 256>>>(W_o, Bhi, Blo, D * D / 4);
    mma_gemm<<<gDD, 256, MG_SMEM>>>(Ahi, Alo, Bhi, Blo, out, BS, D, D);
}